// round 4
// baseline (speedup 1.0000x reference)
#include <cuda_runtime.h>
#include <math.h>

#define B_ 16
#define S_ 2048
#define D_ 1024
#define H_ 128
#define M_ (B_ * S_)   // 32768

// Scratch for Q/K/V projections: 3 x 16 MB
__device__ float g_q[(size_t)M_ * H_];
__device__ float g_k[(size_t)M_ * H_];
__device__ float g_v[(size_t)M_ * H_];

// ---------------------------------------------------------------------------
// QKV projection: C[M,H] = A[M,D] @ W[D,H].  blockIdx.z selects Wq/Wk/Wv.
// 128x128 tile, BK=8, 256 threads, 8x8 micro-tile per thread, register
// prefetch of next global tile.
// ---------------------------------------------------------------------------
__global__ __launch_bounds__(256, 2)
void qkv_gemm_kernel(const float* __restrict__ A,
                     const float* __restrict__ Wq,
                     const float* __restrict__ Wk,
                     const float* __restrict__ Wv)
{
    const float* __restrict__ W;
    float* __restrict__ C;
    if (blockIdx.z == 0)      { W = Wq; C = g_q; }
    else if (blockIdx.z == 1) { W = Wk; C = g_k; }
    else                      { W = Wv; C = g_v; }

    __shared__ float As[8][132];   // A tile stored transposed [k][m]
    __shared__ float Bs[8][132];   // B tile [k][n]

    const int tid = threadIdx.x;
    const int tx  = tid & 15;      // 16 cols of threads
    const int ty  = tid >> 4;      // 16 rows of threads
    const int m0  = blockIdx.x * 128;

    // Global load mapping
    const int arow = tid >> 1;           // 0..127
    const int acol = (tid & 1) * 4;      // 0 or 4
    const int brow = tid >> 5;           // 0..7
    const int bcol = (tid & 31) * 4;     // 0..124

    const float* Aptr = A + (size_t)(m0 + arow) * D_ + acol;
    const float* Wptr = W + (size_t)brow * H_ + bcol;

    float acc[8][8];
#pragma unroll
    for (int i = 0; i < 8; i++)
#pragma unroll
        for (int j = 0; j < 8; j++) acc[i][j] = 0.f;

    float4 a4 = *(const float4*)(Aptr);
    float4 b4 = *(const float4*)(Wptr);

    for (int k0 = 0; k0 < D_; k0 += 8) {
        // commit current tile to smem
        As[acol + 0][arow] = a4.x;
        As[acol + 1][arow] = a4.y;
        As[acol + 2][arow] = a4.z;
        As[acol + 3][arow] = a4.w;
        *(float4*)&Bs[brow][bcol] = b4;
        __syncthreads();

        // prefetch next tile into registers (overlaps with compute below)
        if (k0 + 8 < D_) {
            a4 = *(const float4*)(Aptr + k0 + 8);
            b4 = *(const float4*)(Wptr + (size_t)(k0 + 8) * H_);
        }

#pragma unroll
        for (int kk = 0; kk < 8; kk++) {
            float a[8], b[8];
            *(float4*)&a[0] = *(float4*)&As[kk][ty * 8];
            *(float4*)&a[4] = *(float4*)&As[kk][ty * 8 + 4];
            *(float4*)&b[0] = *(float4*)&Bs[kk][tx * 8];
            *(float4*)&b[4] = *(float4*)&Bs[kk][tx * 8 + 4];
#pragma unroll
            for (int i = 0; i < 8; i++)
#pragma unroll
                for (int j = 0; j < 8; j++)
                    acc[i][j] = fmaf(a[i], b[j], acc[i][j]);
        }
        __syncthreads();
    }

#pragma unroll
    for (int i = 0; i < 8; i++) {
        float* cp = C + (size_t)(m0 + ty * 8 + i) * H_ + tx * 8;
        *(float4*)(cp)     = make_float4(acc[i][0], acc[i][1], acc[i][2], acc[i][3]);
        *(float4*)(cp + 4) = make_float4(acc[i][4], acc[i][5], acc[i][6], acc[i][7]);
    }
}

// ---------------------------------------------------------------------------
// Causal flash attention, fp32.
// Block = 64 query rows, loops over 64-key blocks up to the causal limit.
// 256 threads (16x16). Per thread: 4x4 fragment of S, 4x8 fragment of O.
// Online softmax: m/l/alpha per row in smem, O accumulators in registers.
// ---------------------------------------------------------------------------
#define HP 132   // padded row stride for Q/K/V tiles (128 + 4)
#define SP 68    // padded row stride for S tile (64 + 4)

__global__ __launch_bounds__(256)
void attn_kernel(float* __restrict__ out)
{
    extern __shared__ float sm[];
    float* Qs    = sm;                 // 64*132
    float* Ks    = Qs + 64 * HP;       // 64*132
    float* Vs    = Ks + 64 * HP;       // 64*132
    float* Ss    = Vs + 64 * HP;       // 64*68
    float* row_m = Ss + 64 * SP;       // 64
    float* row_l = row_m + 64;         // 64
    float* row_a = row_l + 64;         // 64

    const int tid = threadIdx.x;
    const int tx  = tid & 15;
    const int ty  = tid >> 4;
    const int qb  = (int)(gridDim.x - 1 - blockIdx.x);  // heavy blocks first
    const int b   = blockIdx.y;

    const float scale = 0.08838834764831845f;  // 128^-0.5

    const size_t qbase = ((size_t)b * S_ + (size_t)qb * 64) * H_;

    // Load Q tile (64x128)
#pragma unroll
    for (int t = 0; t < 8; t++) {
        int idx = tid + t * 256;         // 0..2047
        int r = idx >> 5;                // 0..63
        int c = (idx & 31) * 4;          // 0..124
        *(float4*)&Qs[r * HP + c] = *(const float4*)&g_q[qbase + (size_t)r * H_ + c];
    }
    if (tid < 64) { row_m[tid] = -INFINITY; row_l[tid] = 0.f; }

    float o[4][8];
#pragma unroll
    for (int i = 0; i < 4; i++)
#pragma unroll
        for (int j = 0; j < 8; j++) o[i][j] = 0.f;

    for (int kb = 0; kb <= qb; kb++) {
        __syncthreads();  // previous iteration's consumers done with Ks/Vs/Ss

        const size_t kbase = ((size_t)b * S_ + (size_t)kb * 64) * H_;
#pragma unroll
        for (int t = 0; t < 8; t++) {
            int idx = tid + t * 256;
            int r = idx >> 5;
            int c = (idx & 31) * 4;
            *(float4*)&Ks[r * HP + c] = *(const float4*)&g_k[kbase + (size_t)r * H_ + c];
            *(float4*)&Vs[r * HP + c] = *(const float4*)&g_v[kbase + (size_t)r * H_ + c];
        }
        __syncthreads();

        // ---- S = scale * Q K^T : rows ty*4+i, cols j*16+tx ----
        float s[4][4];
#pragma unroll
        for (int i = 0; i < 4; i++)
#pragma unroll
            for (int j = 0; j < 4; j++) s[i][j] = 0.f;

#pragma unroll 4
        for (int k = 0; k < H_; k += 4) {
            float4 qf[4], kf[4];
#pragma unroll
            for (int i = 0; i < 4; i++) qf[i] = *(float4*)&Qs[(ty * 4 + i) * HP + k];
#pragma unroll
            for (int j = 0; j < 4; j++) kf[j] = *(float4*)&Ks[(j * 16 + tx) * HP + k];
#pragma unroll
            for (int i = 0; i < 4; i++)
#pragma unroll
                for (int j = 0; j < 4; j++) {
                    s[i][j] = fmaf(qf[i].x, kf[j].x, s[i][j]);
                    s[i][j] = fmaf(qf[i].y, kf[j].y, s[i][j]);
                    s[i][j] = fmaf(qf[i].z, kf[j].z, s[i][j]);
                    s[i][j] = fmaf(qf[i].w, kf[j].w, s[i][j]);
                }
        }

        const bool diag = (kb == qb);
#pragma unroll
        for (int i = 0; i < 4; i++) {
            int gr = qb * 64 + ty * 4 + i;
#pragma unroll
            for (int j = 0; j < 4; j++) {
                int gc = kb * 64 + j * 16 + tx;
                float v = s[i][j] * scale;
                if (diag && gc > gr) v = -INFINITY;
                Ss[(ty * 4 + i) * SP + j * 16 + tx] = v;
            }
        }
        __syncthreads();

        // ---- online softmax row pass: one thread per row ----
        if (tid < 64) {
            float* srow = &Ss[tid * SP];
            float m_old = row_m[tid];
            float mx = m_old;
#pragma unroll 8
            for (int c = 0; c < 64; c++) mx = fmaxf(mx, srow[c]);
            float alpha = __expf(m_old - mx);   // 0 on first block (m_old=-inf)
            float sum = 0.f;
#pragma unroll 8
            for (int c = 0; c < 64; c++) {
                float p = __expf(srow[c] - mx); // masked -inf -> 0
                srow[c] = p;
                sum += p;
            }
            row_l[tid] = row_l[tid] * alpha + sum;
            row_m[tid] = mx;
            row_a[tid] = alpha;
        }
        __syncthreads();

        // ---- rescale O and accumulate P @ V ----
        float al[4];
#pragma unroll
        for (int i = 0; i < 4; i++) al[i] = row_a[ty * 4 + i];
#pragma unroll
        for (int i = 0; i < 4; i++)
#pragma unroll
            for (int j = 0; j < 8; j++) o[i][j] *= al[i];

#pragma unroll 4
        for (int kk = 0; kk < 64; kk += 4) {
            float4 p[4];
#pragma unroll
            for (int i = 0; i < 4; i++) p[i] = *(float4*)&Ss[(ty * 4 + i) * SP + kk];
#pragma unroll
            for (int t = 0; t < 4; t++) {
                float4 va = *(float4*)&Vs[(kk + t) * HP + tx * 8];
                float4 vb = *(float4*)&Vs[(kk + t) * HP + tx * 8 + 4];
#pragma unroll
                for (int i = 0; i < 4; i++) {
                    float pv = (t == 0) ? p[i].x : (t == 1) ? p[i].y
                             : (t == 2) ? p[i].z : p[i].w;
                    o[i][0] = fmaf(pv, va.x, o[i][0]);
                    o[i][1] = fmaf(pv, va.y, o[i][1]);
                    o[i][2] = fmaf(pv, va.z, o[i][2]);
                    o[i][3] = fmaf(pv, va.w, o[i][3]);
                    o[i][4] = fmaf(pv, vb.x, o[i][4]);
                    o[i][5] = fmaf(pv, vb.y, o[i][5]);
                    o[i][6] = fmaf(pv, vb.z, o[i][6]);
                    o[i][7] = fmaf(pv, vb.w, o[i][7]);
                }
            }
        }
    }

    // ---- finalize: divide by l and store ----
    float linv[4];
#pragma unroll
    for (int i = 0; i < 4; i++) linv[i] = 1.f / row_l[ty * 4 + i];
#pragma unroll
    for (int i = 0; i < 4; i++) {
        float* op = out + qbase + (size_t)(ty * 4 + i) * H_ + tx * 8;
        *(float4*)(op)     = make_float4(o[i][0] * linv[i], o[i][1] * linv[i],
                                         o[i][2] * linv[i], o[i][3] * linv[i]);
        *(float4*)(op + 4) = make_float4(o[i][4] * linv[i], o[i][5] * linv[i],
                                         o[i][6] * linv[i], o[i][7] * linv[i]);
    }
}

// ---------------------------------------------------------------------------
// Launch
// ---------------------------------------------------------------------------
extern "C" void kernel_launch(void* const* d_in, const int* in_sizes, int n_in,
                              void* d_out, int out_size)
{
    const float* input = (const float*)d_in[0];
    const float* Wq    = (const float*)d_in[1];
    const float* Wk    = (const float*)d_in[2];
    const float* Wv    = (const float*)d_in[3];
    float* out = (float*)d_out;

    // 1) Q/K/V projections
    dim3 gemm_grid(M_ / 128, 1, 3);
    qkv_gemm_kernel<<<gemm_grid, 256>>>(input, Wq, Wk, Wv);

    // 2) causal flash attention
    const size_t smem_bytes = (size_t)(3 * 64 * HP + 64 * SP + 3 * 64) * sizeof(float);
    cudaFuncSetAttribute(attn_kernel,
                         cudaFuncAttributeMaxDynamicSharedMemorySize,
                         (int)smem_bytes);
    attn_kernel<<<dim3(S_ / 64, B_), 256, smem_bytes>>>(out);
}

// round 8
// speedup vs baseline: 1.1637x; 1.1637x over previous
#include <cuda_runtime.h>
#include <math.h>

#define B_ 16
#define S_ 2048
#define D_ 1024
#define H_ 128
#define M_ (B_ * S_)   // 32768

// Scratch for Q/K/V projections: 3 x 16 MB
__device__ float g_q[(size_t)M_ * H_];
__device__ float g_k[(size_t)M_ * H_];
__device__ float g_v[(size_t)M_ * H_];

// ---------------------------------------------------------------------------
// Packed f32x2 helpers (Blackwell FFMA2 path — ptxas never emits this from C++)
// ---------------------------------------------------------------------------
__device__ __forceinline__ unsigned long long pk2(float lo, float hi) {
    unsigned long long r;
    asm("mov.b64 %0, {%1,%2};" : "=l"(r) : "f"(lo), "f"(hi));
    return r;
}
__device__ __forceinline__ float2 upk2(unsigned long long p) {
    float2 r;
    asm("mov.b64 {%0,%1}, %2;" : "=f"(r.x), "=f"(r.y) : "l"(p));
    return r;
}
__device__ __forceinline__ void ffma2(unsigned long long& d,
                                      unsigned long long a,
                                      unsigned long long b) {
    asm("fma.rn.f32x2 %0, %1, %2, %3;" : "=l"(d) : "l"(a), "l"(b), "l"(d));
}
__device__ __forceinline__ void fmul2(unsigned long long& d,
                                      unsigned long long a) {
    asm("mul.rn.f32x2 %0, %0, %1;" : "+l"(d) : "l"(a));
}

// ---------------------------------------------------------------------------
// QKV projection: C[M,H] = A[M,D] @ W[D,H].  blockIdx.z selects Wq/Wk/Wv.
// 128x128 tile, BK=8, 256 threads, 8x8 micro-tile (as 8x4 packed f32x2).
// Thread columns: tx*4..+3 and 64+tx*4..+3  (conflict-free 4*tx bank pattern).
// ---------------------------------------------------------------------------
__global__ __launch_bounds__(256, 2)
void qkv_gemm_kernel(const float* __restrict__ A,
                     const float* __restrict__ Wq,
                     const float* __restrict__ Wk,
                     const float* __restrict__ Wv)
{
    const float* __restrict__ W;
    float* __restrict__ C;
    if (blockIdx.z == 0)      { W = Wq; C = g_q; }
    else if (blockIdx.z == 1) { W = Wk; C = g_k; }
    else                      { W = Wv; C = g_v; }

    __shared__ float As[8][132];   // A tile stored transposed [k][m]
    __shared__ float Bs[8][132];   // B tile [k][n]

    const int tid = threadIdx.x;
    const int tx  = tid & 15;      // 16 cols of threads
    const int ty  = tid >> 4;      // 16 rows of threads
    const int m0  = blockIdx.x * 128;

    const int arow = tid >> 1;           // 0..127
    const int acol = (tid & 1) * 4;      // 0 or 4
    const int brow = tid >> 5;           // 0..7
    const int bcol = (tid & 31) * 4;     // 0..124

    const float* Aptr = A + (size_t)(m0 + arow) * D_ + acol;
    const float* Wptr = W + (size_t)brow * H_ + bcol;

    unsigned long long accp[8][4];
#pragma unroll
    for (int i = 0; i < 8; i++)
#pragma unroll
        for (int j = 0; j < 4; j++) accp[i][j] = 0ull;

    float4 a4 = *(const float4*)(Aptr);
    float4 b4 = *(const float4*)(Wptr);

    for (int k0 = 0; k0 < D_; k0 += 8) {
        As[acol + 0][arow] = a4.x;
        As[acol + 1][arow] = a4.y;
        As[acol + 2][arow] = a4.z;
        As[acol + 3][arow] = a4.w;
        *(float4*)&Bs[brow][bcol] = b4;
        __syncthreads();

        if (k0 + 8 < D_) {
            a4 = *(const float4*)(Aptr + k0 + 8);
            b4 = *(const float4*)(Wptr + (size_t)(k0 + 8) * H_);
        }

#pragma unroll
        for (int kk = 0; kk < 8; kk++) {
            float a[8];
            *(float4*)&a[0] = *(float4*)&As[kk][ty * 8];
            *(float4*)&a[4] = *(float4*)&As[kk][ty * 8 + 4];
            ulonglong2 b01 = *(const ulonglong2*)&Bs[kk][tx * 4];
            ulonglong2 b23 = *(const ulonglong2*)&Bs[kk][64 + tx * 4];
#pragma unroll
            for (int i = 0; i < 8; i++) {
                unsigned long long ap = pk2(a[i], a[i]);
                ffma2(accp[i][0], ap, b01.x);
                ffma2(accp[i][1], ap, b01.y);
                ffma2(accp[i][2], ap, b23.x);
                ffma2(accp[i][3], ap, b23.y);
            }
        }
        __syncthreads();
    }

#pragma unroll
    for (int i = 0; i < 8; i++) {
        float* cp = C + (size_t)(m0 + ty * 8 + i) * H_;
        float2 u0 = upk2(accp[i][0]);
        float2 u1 = upk2(accp[i][1]);
        float2 u2 = upk2(accp[i][2]);
        float2 u3 = upk2(accp[i][3]);
        *(float4*)(cp + tx * 4)      = make_float4(u0.x, u0.y, u1.x, u1.y);
        *(float4*)(cp + 64 + tx * 4) = make_float4(u2.x, u2.y, u3.x, u3.y);
    }
}

// ---------------------------------------------------------------------------
// Causal flash attention, fp32 with packed f32x2 math.
// CTA = 128 query rows, 512 threads (32 ty x 16 tx), loops over 64-key blocks.
// Per thread: 4x4 S fragment (rows ty*4+i, cols j*16+tx), O cols tx*4 / 64+tx*4.
// Online softmax fully in registers (m/l per row replicated over 16 lanes,
// shfl_xor row reductions). No serial row pass.
// ---------------------------------------------------------------------------
#define QP 128   // Q tile row stride (reads are broadcast -> no pad needed)
#define HP 132   // K/V tile row stride (padded)
#define SP 68    // S/P tile row stride (padded)

__global__ __launch_bounds__(512, 1)
void attn_kernel(float* __restrict__ out)
{
    extern __shared__ float sm[];
    float* Qs = sm;                   // 128*128
    float* Ks = Qs + 128 * QP;        // 64*132
    float* Vs = Ks + 64 * HP;         // 64*132
    float* Ss = Vs + 64 * HP;         // 128*68

    const int tid = threadIdx.x;
    const int tx  = tid & 15;
    const int ty  = tid >> 4;                      // 0..31
    const int qb  = (int)(gridDim.x - 1 - blockIdx.x);  // heavy blocks first
    const int b   = blockIdx.y;

    const float scale = 0.08838834764831845f;      // 128^-0.5
    const size_t qbase = ((size_t)b * S_ + (size_t)qb * 128) * H_;

    // Load Q tile (128x128)
#pragma unroll
    for (int t = 0; t < 8; t++) {
        int idx = tid + t * 512;          // 0..4095
        int r = idx >> 5;                 // 0..127
        int c = (idx & 31) * 4;           // 0..124
        *(float4*)&Qs[r * QP + c] = *(const float4*)&g_q[qbase + (size_t)r * H_ + c];
    }

    unsigned long long o2[4][4];
#pragma unroll
    for (int i = 0; i < 4; i++)
#pragma unroll
        for (int j = 0; j < 4; j++) o2[i][j] = 0ull;

    float m_old[4], l_run[4];
#pragma unroll
    for (int i = 0; i < 4; i++) { m_old[i] = -INFINITY; l_run[i] = 0.f; }

    const int kb_end = 2 * qb + 1;
    for (int kb = 0; kb <= kb_end; kb++) {
        __syncthreads();   // prior iteration done with Ks/Vs/Ss

        const size_t kbase = ((size_t)b * S_ + (size_t)kb * 64) * H_;
#pragma unroll
        for (int t = 0; t < 4; t++) {
            int idx = tid + t * 512;
            int r = idx >> 5;             // 0..63
            int c = (idx & 31) * 4;
            *(float4*)&Ks[r * HP + c] = *(const float4*)&g_k[kbase + (size_t)r * H_ + c];
            *(float4*)&Vs[r * HP + c] = *(const float4*)&g_v[kbase + (size_t)r * H_ + c];
        }
        __syncthreads();

        // ---- S = Q K^T (packed over k; combine halves at the end) ----
        unsigned long long s2[4][4];
#pragma unroll
        for (int i = 0; i < 4; i++)
#pragma unroll
            for (int j = 0; j < 4; j++) s2[i][j] = 0ull;

#pragma unroll 4
        for (int k = 0; k < H_; k += 4) {
            ulonglong2 q2[4], k2[4];
#pragma unroll
            for (int i = 0; i < 4; i++)
                q2[i] = *(const ulonglong2*)&Qs[(ty * 4 + i) * QP + k];
#pragma unroll
            for (int j = 0; j < 4; j++)
                k2[j] = *(const ulonglong2*)&Ks[(j * 16 + tx) * HP + k];
#pragma unroll
            for (int i = 0; i < 4; i++)
#pragma unroll
                for (int j = 0; j < 4; j++) {
                    ffma2(s2[i][j], q2[i].x, k2[j].x);
                    ffma2(s2[i][j], q2[i].y, k2[j].y);
                }
        }

        // ---- scale + mask + online softmax (registers + shfl) ----
        const bool need_mask = (kb >= 2 * qb);
#pragma unroll
        for (int i = 0; i < 4; i++) {
            const int gr = qb * 128 + ty * 4 + i;
            float p[4];
            float mx = -INFINITY;
#pragma unroll
            for (int j = 0; j < 4; j++) {
                float2 t2 = upk2(s2[i][j]);
                float v = (t2.x + t2.y) * scale;
                if (need_mask && (kb * 64 + j * 16 + tx) > gr) v = -INFINITY;
                p[j] = v;
                mx = fmaxf(mx, v);
            }
#pragma unroll
            for (int off = 1; off < 16; off <<= 1)
                mx = fmaxf(mx, __shfl_xor_sync(0xffffffffu, mx, off));

            float mn = fmaxf(m_old[i], mx);
            float al = __expf(m_old[i] - mn);   // 0 on first block
            float sum = 0.f;
#pragma unroll
            for (int j = 0; j < 4; j++) {
                float e = __expf(p[j] - mn);    // masked -inf -> 0
                p[j] = e;
                sum += e;
            }
#pragma unroll
            for (int off = 1; off < 16; off <<= 1)
                sum += __shfl_xor_sync(0xffffffffu, sum, off);

            l_run[i] = l_run[i] * al + sum;
            m_old[i] = mn;

            unsigned long long a2 = pk2(al, al);
#pragma unroll
            for (int jp = 0; jp < 4; jp++) fmul2(o2[i][jp], a2);

#pragma unroll
            for (int j = 0; j < 4; j++)
                Ss[(ty * 4 + i) * SP + j * 16 + tx] = p[j];
        }
        __syncthreads();

        // ---- O += P @ V  (packed over output columns) ----
#pragma unroll 2
        for (int kk = 0; kk < 64; kk += 4) {
            float4 p4[4];
#pragma unroll
            for (int i = 0; i < 4; i++)
                p4[i] = *(float4*)&Ss[(ty * 4 + i) * SP + kk];
#pragma unroll
            for (int t = 0; t < 4; t++) {
                ulonglong2 va = *(const ulonglong2*)&Vs[(kk + t) * HP + tx * 4];
                ulonglong2 vb = *(const ulonglong2*)&Vs[(kk + t) * HP + 64 + tx * 4];
#pragma unroll
                for (int i = 0; i < 4; i++) {
                    float pv = (t == 0) ? p4[i].x : (t == 1) ? p4[i].y
                             : (t == 2) ? p4[i].z : p4[i].w;
                    unsigned long long pp = pk2(pv, pv);
                    ffma2(o2[i][0], pp, va.x);
                    ffma2(o2[i][1], pp, va.y);
                    ffma2(o2[i][2], pp, vb.x);
                    ffma2(o2[i][3], pp, vb.y);
                }
            }
        }
    }

    // ---- finalize: divide by l and store ----
#pragma unroll
    for (int i = 0; i < 4; i++) {
        float linv = 1.f / l_run[i];
        float2 u0 = upk2(o2[i][0]);
        float2 u1 = upk2(o2[i][1]);
        float2 u2 = upk2(o2[i][2]);
        float2 u3 = upk2(o2[i][3]);
        float* op = out + qbase + (size_t)(ty * 4 + i) * H_;
        *(float4*)(op + tx * 4) =
            make_float4(u0.x * linv, u0.y * linv, u1.x * linv, u1.y * linv);
        *(float4*)(op + 64 + tx * 4) =
            make_float4(u2.x * linv, u2.y * linv, u3.x * linv, u3.y * linv);
    }
}

// ---------------------------------------------------------------------------
// Launch
// ---------------------------------------------------------------------------
extern "C" void kernel_launch(void* const* d_in, const int* in_sizes, int n_in,
                              void* d_out, int out_size)
{
    const float* input = (const float*)d_in[0];
    const float* Wq    = (const float*)d_in[1];
    const float* Wk    = (const float*)d_in[2];
    const float* Wv    = (const float*)d_in[3];
    float* out = (float*)d_out;

    // 1) Q/K/V projections
    dim3 gemm_grid(M_ / 128, 1, 3);
    qkv_gemm_kernel<<<gemm_grid, 256>>>(input, Wq, Wk, Wv);

    // 2) causal flash attention (128-row Q blocks, heavy-first)
    const size_t smem_bytes =
        (size_t)(128 * QP + 2 * 64 * HP + 128 * SP) * sizeof(float);
    cudaFuncSetAttribute(attn_kernel,
                         cudaFuncAttributeMaxDynamicSharedMemorySize,
                         (int)smem_bytes);
    attn_kernel<<<dim3(S_ / 128, B_), 512, smem_bytes>>>(out);
}

// round 10
// speedup vs baseline: 1.5451x; 1.3278x over previous
#include <cuda_runtime.h>
#include <cuda_bf16.h>
#include <math.h>
#include <stdint.h>

#define B_ 16
#define S_ 2048
#define D_ 1024
#define H_ 128
#define M_ (B_ * S_)   // 32768

// Scratch for Q/K/V projections: 3 x 16 MB
__device__ float g_q[(size_t)M_ * H_];
__device__ float g_k[(size_t)M_ * H_];
__device__ float g_v[(size_t)M_ * H_];

// ===========================================================================
// Baseline-PTX tensor-core helpers (sm_80+ instructions, valid on compute_103)
// ===========================================================================
__device__ __forceinline__ uint32_t smem_u32(const void* p) {
    uint32_t a;
    asm("{ .reg .u64 t; cvta.to.shared.u64 t, %1; cvt.u32.u64 %0, t; }"
        : "=r"(a) : "l"(p));
    return a;
}

__device__ __forceinline__ void ldsm4(uint32_t r[4], uint32_t addr) {
    asm volatile("ldmatrix.sync.aligned.m8n8.x4.shared.b16 {%0,%1,%2,%3}, [%4];"
                 : "=r"(r[0]), "=r"(r[1]), "=r"(r[2]), "=r"(r[3]) : "r"(addr));
}
__device__ __forceinline__ void ldsm4t(uint32_t r[4], uint32_t addr) {
    asm volatile("ldmatrix.sync.aligned.m8n8.x4.trans.shared.b16 {%0,%1,%2,%3}, [%4];"
                 : "=r"(r[0]), "=r"(r[1]), "=r"(r[2]), "=r"(r[3]) : "r"(addr));
}

// D += A * B  (m16n8k16, bf16 x bf16 -> fp32)
__device__ __forceinline__ void mma16816(float c[4], const uint32_t a[4],
                                         uint32_t b0, uint32_t b1) {
    asm volatile(
        "mma.sync.aligned.m16n8k16.row.col.f32.bf16.bf16.f32 "
        "{%0,%1,%2,%3}, {%4,%5,%6,%7}, {%8,%9}, {%0,%1,%2,%3};"
        : "+f"(c[0]), "+f"(c[1]), "+f"(c[2]), "+f"(c[3])
        : "r"(a[0]), "r"(a[1]), "r"(a[2]), "r"(a[3]), "r"(b0), "r"(b1));
}

// Split two fp32 into packed bf16 hi-pair and lo-pair (bf16x3 emulation).
__device__ __forceinline__ void split2(float x0, float x1,
                                       uint32_t& hi, uint32_t& lo) {
    __nv_bfloat16 h0 = __float2bfloat16_rn(x0);
    __nv_bfloat16 h1 = __float2bfloat16_rn(x1);
    __nv_bfloat162 hp;
    hp.x = h0; hp.y = h1;
    hi = *reinterpret_cast<uint32_t*>(&hp);
    __nv_bfloat162 lp = __floats2bfloat162_rn(x0 - __bfloat162float(h0),
                                              x1 - __bfloat162float(h1));
    lo = *reinterpret_cast<uint32_t*>(&lp);
}
__device__ __forceinline__ void split_store(char* sm, int hoff, int loff,
                                            float x0, float x1) {
    uint32_t hi, lo;
    split2(x0, x1, hi, lo);
    *(uint32_t*)(sm + hoff) = hi;
    *(uint32_t*)(sm + loff) = lo;
}

// ===========================================================================
// QKV GEMM: C[M,H] = A[M,D] @ W[D,H], blockIdx.y selects Wq/Wk/Wv.
// 128x128 block tile, BK=64, 8 warps as 4(M)x2(N): warp tile 32x64.
// bf16x3 split operands in smem. Padded rows (144B) -> conflict-free ldmatrix.
// ===========================================================================
#define GST   144        // smem row stride bytes (64 bf16 + 8 pad)
#define G_AH  0
#define G_AL  18432
#define G_BH  36864
#define G_BL  55296
#define G_SMEM 73728

__global__ __launch_bounds__(256, 1)
void qkv_mma(const float* __restrict__ A,
             const float* __restrict__ Wq,
             const float* __restrict__ Wk,
             const float* __restrict__ Wv)
{
    extern __shared__ char sm[];
    const uint32_t sb = smem_u32(sm);
    const int tid  = threadIdx.x;
    const int lane = tid & 31;
    const int wid  = tid >> 5;
    const int wm   = wid & 3;      // 32-row slice
    const int wn   = wid >> 2;     // 64-col slice
    const int m0   = blockIdx.x * 128;

    const float* __restrict__ W;
    float* __restrict__ C;
    if (blockIdx.y == 0)      { W = Wq; C = g_q; }
    else if (blockIdx.y == 1) { W = Wk; C = g_k; }
    else                      { W = Wv; C = g_v; }

    // ldmatrix per-lane offsets
    const int a_r = lane & 15;                       // A-frag row within 16
    const int a_k = (lane >> 4) * 16;                // A-frag k byte offset
    const int b_n = (lane & 7) + ((lane >> 4) << 3); // B-frag n within 16
    const int b_k = ((lane >> 3) & 1) * 16;          // B-frag k byte offset

    float acc[2][8][4];
#pragma unroll
    for (int i = 0; i < 2; i++)
#pragma unroll
        for (int j = 0; j < 8; j++)
#pragma unroll
            for (int e = 0; e < 4; e++) acc[i][j][e] = 0.f;

    for (int c = 0; c < 16; c++) {
        const int c0 = c * 64;
        __syncthreads();   // previous chunk's consumers done

        // A tile 128x64 fp32 -> split bf16 [m][k]
        for (int it = tid; it < 4096; it += 256) {
            int m = it >> 5, kp = it & 31;
            float2 a2 = *(const float2*)(A + (size_t)(m0 + m) * D_ + c0 + 2 * kp);
            split_store(sm, G_AH + m * GST + kp * 4, G_AL + m * GST + kp * 4,
                        a2.x, a2.y);
        }
        // W tile 64x128 fp32 -> split bf16 transposed [n][k]
        for (int it = tid; it < 4096; it += 256) {
            int n = it & 127, kp = it >> 7;
            float x0 = W[(size_t)(c0 + 2 * kp) * H_ + n];
            float x1 = W[(size_t)(c0 + 2 * kp + 1) * H_ + n];
            split_store(sm, G_BH + n * GST + kp * 4, G_BL + n * GST + kp * 4,
                        x0, x1);
        }
        __syncthreads();

#pragma unroll
        for (int ks = 0; ks < 4; ks++) {
            const int kb = ks * 32;
            uint32_t ah[2][4], al[2][4];
#pragma unroll
            for (int mt = 0; mt < 2; mt++) {
                uint32_t base = sb + (uint32_t)((wm * 32 + mt * 16 + a_r) * GST + kb + a_k);
                ldsm4(ah[mt], base + G_AH);
                ldsm4(al[mt], base + G_AL);
            }
            uint32_t bh[8][2], bl[8][2];
#pragma unroll
            for (int ntp = 0; ntp < 4; ntp++) {
                uint32_t base = sb + (uint32_t)((wn * 64 + ntp * 16 + b_n) * GST + kb + b_k);
                uint32_t r4[4];
                ldsm4(r4, base + G_BH);
                bh[2 * ntp][0] = r4[0]; bh[2 * ntp][1] = r4[1];
                bh[2 * ntp + 1][0] = r4[2]; bh[2 * ntp + 1][1] = r4[3];
                ldsm4(r4, base + G_BL);
                bl[2 * ntp][0] = r4[0]; bl[2 * ntp][1] = r4[1];
                bl[2 * ntp + 1][0] = r4[2]; bl[2 * ntp + 1][1] = r4[3];
            }
#pragma unroll
            for (int mt = 0; mt < 2; mt++)
#pragma unroll
                for (int nt = 0; nt < 8; nt++) {
                    mma16816(acc[mt][nt], ah[mt], bh[nt][0], bh[nt][1]);
                    mma16816(acc[mt][nt], ah[mt], bl[nt][0], bl[nt][1]);
                    mma16816(acc[mt][nt], al[mt], bh[nt][0], bh[nt][1]);
                }
        }
    }

    // Epilogue: c0,c1 -> row lane/4 ; c2,c3 -> row+8 ; cols (lane&3)*2
#pragma unroll
    for (int mt = 0; mt < 2; mt++)
#pragma unroll
        for (int nt = 0; nt < 8; nt++) {
            int r  = m0 + wm * 32 + mt * 16 + (lane >> 2);
            int cc = wn * 64 + nt * 8 + (lane & 3) * 2;
            *(float2*)(C + (size_t)r * H_ + cc) =
                make_float2(acc[mt][nt][0], acc[mt][nt][1]);
            *(float2*)(C + (size_t)(r + 8) * H_ + cc) =
                make_float2(acc[mt][nt][2], acc[mt][nt][3]);
        }
}

// ===========================================================================
// Causal flash attention on mma.sync, bf16x3 split.
// CTA = 128 q rows, 256 threads, 8 warps x 16 rows each (warps own full rows).
// S accum in registers; P fragments formed in-register (no smem round-trip).
// V kept [keys][h] in smem; transposed by ldmatrix.trans for the PV MMA.
// ===========================================================================
#define AST   272       // smem row stride bytes (128 bf16 + 8 pad)
#define A_QH  0
#define A_QL  34816
#define A_KH  69632
#define A_KL  87040
#define A_VH  104448
#define A_VL  121856
#define A_SMEM 139264

__global__ __launch_bounds__(256, 1)
void attn_mma(float* __restrict__ out)
{
    extern __shared__ char sm[];
    const uint32_t sb = smem_u32(sm);
    const int tid  = threadIdx.x;
    const int lane = tid & 31;
    const int wid  = tid >> 5;
    const int qb   = (int)(gridDim.x - 1 - blockIdx.x);  // heavy-first
    const int b    = blockIdx.y;
    const float scale = 0.08838834764831845f;            // 128^-0.5

    const int a_r = lane & 15;
    const int a_k = (lane >> 4) * 16;
    const int b_n = (lane & 7) + ((lane >> 4) << 3);
    const int b_k = ((lane >> 3) & 1) * 16;
    const int v_key = lane & 15;
    const int v_h   = (lane >> 4) * 16;

    const size_t qbase = ((size_t)b * S_ + (size_t)qb * 128) * H_;

    // Q tile 128x128 (scale folded in) -> split bf16
    for (int it = tid; it < 8192; it += 256) {
        int r = it >> 6, p = it & 63;
        float2 q2 = *(const float2*)&g_q[qbase + (size_t)r * H_ + 2 * p];
        split_store(sm, A_QH + r * AST + p * 4, A_QL + r * AST + p * 4,
                    q2.x * scale, q2.y * scale);
    }

    float O[16][4];
#pragma unroll
    for (int nt = 0; nt < 16; nt++)
#pragma unroll
        for (int e = 0; e < 4; e++) O[nt][e] = 0.f;
    float mA = -INFINITY, mB = -INFINITY, lA = 0.f, lB = 0.f;

    const int kb_end = 2 * qb + 1;
    for (int kb = 0; kb <= kb_end; kb++) {
        __syncthreads();   // prior iteration done reading K/V smem
        const size_t kbase = ((size_t)b * S_ + (size_t)kb * 64) * H_;
        for (int it = tid; it < 4096; it += 256) {
            int r = it >> 6, p = it & 63;
            float2 k2 = *(const float2*)&g_k[kbase + (size_t)r * H_ + 2 * p];
            split_store(sm, A_KH + r * AST + p * 4, A_KL + r * AST + p * 4,
                        k2.x, k2.y);
            float2 v2 = *(const float2*)&g_v[kbase + (size_t)r * H_ + 2 * p];
            split_store(sm, A_VH + r * AST + p * 4, A_VL + r * AST + p * 4,
                        v2.x, v2.y);
        }
        __syncthreads();

        // ---- S = Q K^T : warp rows [wid*16, +16), cols 64 ----
        float s[8][4];
#pragma unroll
        for (int nt = 0; nt < 8; nt++)
#pragma unroll
            for (int e = 0; e < 4; e++) s[nt][e] = 0.f;

#pragma unroll
        for (int ks = 0; ks < 8; ks++) {
            const int kbyte = ks * 32;
            uint32_t qh[4], ql[4];
            uint32_t qa = sb + (uint32_t)((wid * 16 + a_r) * AST + kbyte + a_k);
            ldsm4(qh, qa + A_QH);
            ldsm4(ql, qa + A_QL);
            uint32_t kh[8][2], kl[8][2];
#pragma unroll
            for (int ntp = 0; ntp < 4; ntp++) {
                uint32_t ka = sb + (uint32_t)((ntp * 16 + b_n) * AST + kbyte + b_k);
                uint32_t r4[4];
                ldsm4(r4, ka + A_KH);
                kh[2 * ntp][0] = r4[0]; kh[2 * ntp][1] = r4[1];
                kh[2 * ntp + 1][0] = r4[2]; kh[2 * ntp + 1][1] = r4[3];
                ldsm4(r4, ka + A_KL);
                kl[2 * ntp][0] = r4[0]; kl[2 * ntp][1] = r4[1];
                kl[2 * ntp + 1][0] = r4[2]; kl[2 * ntp + 1][1] = r4[3];
            }
#pragma unroll
            for (int nt = 0; nt < 8; nt++) {
                mma16816(s[nt], qh, kh[nt][0], kh[nt][1]);
                mma16816(s[nt], qh, kl[nt][0], kl[nt][1]);
                mma16816(s[nt], ql, kh[nt][0], kh[nt][1]);
            }
        }

        // ---- mask + online softmax (rows rA = wid*16+lane/4, rB = rA+8) ----
        const int grA = qb * 128 + wid * 16 + (lane >> 2);
        if (kb >= 2 * qb) {
#pragma unroll
            for (int nt = 0; nt < 8; nt++) {
                int c0 = kb * 64 + nt * 8 + (lane & 3) * 2;
                if (c0 > grA)         s[nt][0] = -INFINITY;
                if (c0 + 1 > grA)     s[nt][1] = -INFINITY;
                if (c0 > grA + 8)     s[nt][2] = -INFINITY;
                if (c0 + 1 > grA + 8) s[nt][3] = -INFINITY;
            }
        }
        float mxA = -INFINITY, mxB = -INFINITY;
#pragma unroll
        for (int nt = 0; nt < 8; nt++) {
            mxA = fmaxf(mxA, fmaxf(s[nt][0], s[nt][1]));
            mxB = fmaxf(mxB, fmaxf(s[nt][2], s[nt][3]));
        }
        mxA = fmaxf(mxA, __shfl_xor_sync(0xffffffffu, mxA, 1));
        mxA = fmaxf(mxA, __shfl_xor_sync(0xffffffffu, mxA, 2));
        mxB = fmaxf(mxB, __shfl_xor_sync(0xffffffffu, mxB, 1));
        mxB = fmaxf(mxB, __shfl_xor_sync(0xffffffffu, mxB, 2));

        float mnA = fmaxf(mA, mxA), mnB = fmaxf(mB, mxB);
        float alA = __expf(mA - mnA), alB = __expf(mB - mnB);
        float suA = 0.f, suB = 0.f;
#pragma unroll
        for (int nt = 0; nt < 8; nt++) {
            s[nt][0] = __expf(s[nt][0] - mnA);
            s[nt][1] = __expf(s[nt][1] - mnA);
            s[nt][2] = __expf(s[nt][2] - mnB);
            s[nt][3] = __expf(s[nt][3] - mnB);
            suA += s[nt][0] + s[nt][1];
            suB += s[nt][2] + s[nt][3];
        }
        suA += __shfl_xor_sync(0xffffffffu, suA, 1);
        suA += __shfl_xor_sync(0xffffffffu, suA, 2);
        suB += __shfl_xor_sync(0xffffffffu, suB, 1);
        suB += __shfl_xor_sync(0xffffffffu, suB, 2);
        lA = lA * alA + suA;  mA = mnA;
        lB = lB * alB + suB;  mB = mnB;

        // rescale O
#pragma unroll
        for (int nt = 0; nt < 16; nt++) {
            O[nt][0] *= alA; O[nt][1] *= alA;
            O[nt][2] *= alB; O[nt][3] *= alB;
        }

        // ---- O += P @ V : P frags built in-register from s ----
#pragma unroll
        for (int t = 0; t < 4; t++) {
            uint32_t ph[4], pl[4];
            split2(s[2 * t][0],     s[2 * t][1],     ph[0], pl[0]);
            split2(s[2 * t][2],     s[2 * t][3],     ph[1], pl[1]);
            split2(s[2 * t + 1][0], s[2 * t + 1][1], ph[2], pl[2]);
            split2(s[2 * t + 1][2], s[2 * t + 1][3], ph[3], pl[3]);
#pragma unroll
            for (int ntp = 0; ntp < 8; ntp++) {
                uint32_t va = sb + (uint32_t)((t * 16 + v_key) * AST + ntp * 32 + v_h);
                uint32_t vh[4], vl[4];
                ldsm4t(vh, va + A_VH);
                ldsm4t(vl, va + A_VL);
                mma16816(O[2 * ntp],     ph, vh[0], vh[1]);
                mma16816(O[2 * ntp],     ph, vl[0], vl[1]);
                mma16816(O[2 * ntp],     pl, vh[0], vh[1]);
                mma16816(O[2 * ntp + 1], ph, vh[2], vh[3]);
                mma16816(O[2 * ntp + 1], ph, vl[2], vl[3]);
                mma16816(O[2 * ntp + 1], pl, vh[2], vh[3]);
            }
        }
    }

    // ---- finalize: divide by l and store ----
    const float liA = 1.f / lA, liB = 1.f / lB;
    const int rA = qb * 128 + wid * 16 + (lane >> 2);
#pragma unroll
    for (int nt = 0; nt < 16; nt++) {
        int cc = nt * 8 + (lane & 3) * 2;
        *(float2*)(out + ((size_t)b * S_ + rA) * H_ + cc) =
            make_float2(O[nt][0] * liA, O[nt][1] * liA);
        *(float2*)(out + ((size_t)b * S_ + rA + 8) * H_ + cc) =
            make_float2(O[nt][2] * liB, O[nt][3] * liB);
    }
}

// ===========================================================================
// Launch
// ===========================================================================
extern "C" void kernel_launch(void* const* d_in, const int* in_sizes, int n_in,
                              void* d_out, int out_size)
{
    const float* input = (const float*)d_in[0];
    const float* Wq    = (const float*)d_in[1];
    const float* Wk    = (const float*)d_in[2];
    const float* Wv    = (const float*)d_in[3];
    float* out = (float*)d_out;

    cudaFuncSetAttribute(qkv_mma,
                         cudaFuncAttributeMaxDynamicSharedMemorySize, G_SMEM);
    cudaFuncSetAttribute(attn_mma,
                         cudaFuncAttributeMaxDynamicSharedMemorySize, A_SMEM);

    qkv_mma<<<dim3(M_ / 128, 3), 256, G_SMEM>>>(input, Wq, Wk, Wv);
    attn_mma<<<dim3(S_ / 128, B_), 256, A_SMEM>>>(out);
}

// round 12
// speedup vs baseline: 2.6891x; 1.7404x over previous
#include <cuda_runtime.h>
#include <cuda_bf16.h>
#include <math.h>
#include <stdint.h>

#define B_ 16
#define S_ 2048
#define D_ 1024
#define H_ 128
#define M_ (B_ * S_)   // 32768

// Split operands in global (bf16 hi/lo)
__device__ __nv_bfloat16 g_ah[(size_t)M_ * D_];   // input hi
__device__ __nv_bfloat16 g_al[(size_t)M_ * D_];   // input lo
__device__ __nv_bfloat16 g_wth[3 * H_ * D_];      // W transposed [mat][n][k] hi
__device__ __nv_bfloat16 g_wtl[3 * H_ * D_];      // lo
__device__ __nv_bfloat16 g_qh[(size_t)M_ * H_], g_ql[(size_t)M_ * H_];
__device__ __nv_bfloat16 g_kh[(size_t)M_ * H_], g_kl[(size_t)M_ * H_];
__device__ __nv_bfloat16 g_vh[(size_t)M_ * H_], g_vl[(size_t)M_ * H_];

// ===========================================================================
// Helpers
// ===========================================================================
__device__ __forceinline__ uint32_t smem_u32(const void* p) {
    uint32_t a;
    asm("{ .reg .u64 t; cvta.to.shared.u64 t, %1; cvt.u32.u64 %0, t; }"
        : "=r"(a) : "l"(p));
    return a;
}
__device__ __forceinline__ void ldsm4(uint32_t r[4], uint32_t addr) {
    asm volatile("ldmatrix.sync.aligned.m8n8.x4.shared.b16 {%0,%1,%2,%3}, [%4];"
                 : "=r"(r[0]), "=r"(r[1]), "=r"(r[2]), "=r"(r[3]) : "r"(addr));
}
__device__ __forceinline__ void ldsm4t(uint32_t r[4], uint32_t addr) {
    asm volatile("ldmatrix.sync.aligned.m8n8.x4.trans.shared.b16 {%0,%1,%2,%3}, [%4];"
                 : "=r"(r[0]), "=r"(r[1]), "=r"(r[2]), "=r"(r[3]) : "r"(addr));
}
__device__ __forceinline__ void mma16816(float c[4], const uint32_t a[4],
                                         uint32_t b0, uint32_t b1) {
    asm volatile(
        "mma.sync.aligned.m16n8k16.row.col.f32.bf16.bf16.f32 "
        "{%0,%1,%2,%3}, {%4,%5,%6,%7}, {%8,%9}, {%0,%1,%2,%3};"
        : "+f"(c[0]), "+f"(c[1]), "+f"(c[2]), "+f"(c[3])
        : "r"(a[0]), "r"(a[1]), "r"(a[2]), "r"(a[3]), "r"(b0), "r"(b1));
}
__device__ __forceinline__ void split2(float x0, float x1,
                                       uint32_t& hi, uint32_t& lo) {
    __nv_bfloat16 h0 = __float2bfloat16_rn(x0);
    __nv_bfloat16 h1 = __float2bfloat16_rn(x1);
    __nv_bfloat162 hp; hp.x = h0; hp.y = h1;
    hi = *reinterpret_cast<uint32_t*>(&hp);
    __nv_bfloat162 lp = __floats2bfloat162_rn(x0 - __bfloat162float(h0),
                                              x1 - __bfloat162float(h1));
    lo = *reinterpret_cast<uint32_t*>(&lp);
}
__device__ __forceinline__ void cpa(uint32_t dst, const void* src) {
    asm volatile("cp.async.cg.shared.global [%0], [%1], 16;"
                 :: "r"(dst), "l"(src) : "memory");
}
#define CP_COMMIT() asm volatile("cp.async.commit_group;" ::: "memory")
#define CP_WAIT(n)  asm volatile("cp.async.wait_group %0;" :: "n"(n) : "memory")

// ===========================================================================
// Convert kernels: fp32 -> split bf16 (once, outside the hot loops)
// ===========================================================================
__global__ __launch_bounds__(256)
void conv_a(const float* __restrict__ A)
{
    size_t i = ((size_t)blockIdx.x * 256 + threadIdx.x) * 4;
    float4 v = *(const float4*)(A + i);
    uint32_t h0, l0, h1, l1;
    split2(v.x, v.y, h0, l0);
    split2(v.z, v.w, h1, l1);
    *(uint2*)&g_ah[i] = make_uint2(h0, h1);
    *(uint2*)&g_al[i] = make_uint2(l0, l1);
}

__global__ __launch_bounds__(256)
void conv_w(const float* __restrict__ Wq, const float* __restrict__ Wk,
            const float* __restrict__ Wv)
{
    const int mat = blockIdx.y;
    const float* W = (mat == 0) ? Wq : (mat == 1) ? Wk : Wv;
    int idx = blockIdx.x * 256 + threadIdx.x;   // 0..131071
    int k = idx >> 7, n = idx & 127;
    float x = W[(size_t)k * H_ + n];
    __nv_bfloat16 h = __float2bfloat16_rn(x);
    size_t o = (size_t)mat * (H_ * D_) + (size_t)n * D_ + k;
    g_wth[o] = h;
    g_wtl[o] = __float2bfloat16_rn(x - __bfloat162float(h));
}

// ===========================================================================
// QKV GEMM: C[M,H] = A[M,D] @ W[D,H], blockIdx.y selects matrix.
// 128x128 tile, BK=64, 8 warps (4Mx2N), cp.async double-buffered stages.
// Outputs written as split bf16 (scale folded into Q).
// ===========================================================================
#define GST     144       // smem row stride bytes (64 bf16 + pad)
#define G_STAGE 73728     // Ah 0 | Al 18432 | Bh 36864 | Bl 55296
#define G_SMEM  147456

__global__ __launch_bounds__(256, 1)
void qkv_mma(void)
{
    extern __shared__ char sm[];
    const uint32_t sb = smem_u32(sm);
    const int tid  = threadIdx.x;
    const int lane = tid & 31;
    const int wid  = tid >> 5;
    const int wm   = wid & 3;
    const int wn   = wid >> 2;
    const int m0   = blockIdx.x * 128;
    const int mat  = blockIdx.y;

    const int a_r = lane & 15;
    const int a_k = (lane >> 4) * 16;
    const int b_n = (lane & 7) + ((lane >> 4) << 3);
    const int b_k = ((lane >> 3) & 1) * 16;

    const __nv_bfloat16* wth = g_wth + (size_t)mat * (H_ * D_);
    const __nv_bfloat16* wtl = g_wtl + (size_t)mat * (H_ * D_);

    auto issue = [&](int c, int s) {
        const int c0 = c * 64;
        const uint32_t sbase = sb + s * G_STAGE;
#pragma unroll
        for (int j = 0; j < 16; j++) {
            int it   = tid + j * 256;
            int tile = it >> 10;          // 0:Ah 1:Al 2:Bh 3:Bl
            int r    = (it >> 3) & 127;
            int seg  = it & 7;
            const __nv_bfloat16* src;
            if (tile == 0)      src = g_ah + (size_t)(m0 + r) * D_ + c0 + seg * 8;
            else if (tile == 1) src = g_al + (size_t)(m0 + r) * D_ + c0 + seg * 8;
            else if (tile == 2) src = wth + (size_t)r * D_ + c0 + seg * 8;
            else                src = wtl + (size_t)r * D_ + c0 + seg * 8;
            cpa(sbase + tile * 18432 + r * GST + seg * 16, src);
        }
    };

    float acc[2][8][4];
#pragma unroll
    for (int i = 0; i < 2; i++)
#pragma unroll
        for (int j = 0; j < 8; j++)
#pragma unroll
            for (int e = 0; e < 4; e++) acc[i][j][e] = 0.f;

    issue(0, 0);
    CP_COMMIT();

    for (int c = 0; c < 16; c++) {
        if (c + 1 < 16) {
            issue(c + 1, (c + 1) & 1);
            CP_COMMIT();
            CP_WAIT(1);
        } else {
            CP_WAIT(0);
        }
        __syncthreads();

        const uint32_t stg = sb + (c & 1) * G_STAGE;
#pragma unroll
        for (int ks = 0; ks < 4; ks++) {
            const int kb = ks * 32;
            uint32_t ah[2][4], al[2][4];
#pragma unroll
            for (int mt = 0; mt < 2; mt++) {
                uint32_t base = stg + (uint32_t)((wm * 32 + mt * 16 + a_r) * GST + kb + a_k);
                ldsm4(ah[mt], base);
                ldsm4(al[mt], base + 18432);
            }
            uint32_t bh[8][2], bl[8][2];
#pragma unroll
            for (int ntp = 0; ntp < 4; ntp++) {
                uint32_t base = stg + 36864 +
                    (uint32_t)((wn * 64 + ntp * 16 + b_n) * GST + kb + b_k);
                uint32_t r4[4];
                ldsm4(r4, base);
                bh[2 * ntp][0] = r4[0]; bh[2 * ntp][1] = r4[1];
                bh[2 * ntp + 1][0] = r4[2]; bh[2 * ntp + 1][1] = r4[3];
                ldsm4(r4, base + 18432);
                bl[2 * ntp][0] = r4[0]; bl[2 * ntp][1] = r4[1];
                bl[2 * ntp + 1][0] = r4[2]; bl[2 * ntp + 1][1] = r4[3];
            }
#pragma unroll
            for (int mt = 0; mt < 2; mt++)
#pragma unroll
                for (int nt = 0; nt < 8; nt++) {
                    mma16816(acc[mt][nt], ah[mt], bh[nt][0], bh[nt][1]);
                    mma16816(acc[mt][nt], ah[mt], bl[nt][0], bl[nt][1]);
                    mma16816(acc[mt][nt], al[mt], bh[nt][0], bh[nt][1]);
                }
        }
        __syncthreads();
    }

    // Epilogue: write split bf16; fold softmax scale into Q
    const float qs = (mat == 0) ? 0.08838834764831845f : 1.f;
    __nv_bfloat16* Ch = (mat == 0) ? g_qh : (mat == 1) ? g_kh : g_vh;
    __nv_bfloat16* Cl = (mat == 0) ? g_ql : (mat == 1) ? g_kl : g_vl;
#pragma unroll
    for (int mt = 0; mt < 2; mt++)
#pragma unroll
        for (int nt = 0; nt < 8; nt++) {
            int r  = m0 + wm * 32 + mt * 16 + (lane >> 2);
            int cc = wn * 64 + nt * 8 + (lane & 3) * 2;
            uint32_t hi, lo;
            split2(acc[mt][nt][0] * qs, acc[mt][nt][1] * qs, hi, lo);
            *(uint32_t*)&Ch[(size_t)r * H_ + cc] = hi;
            *(uint32_t*)&Cl[(size_t)r * H_ + cc] = lo;
            split2(acc[mt][nt][2] * qs, acc[mt][nt][3] * qs, hi, lo);
            *(uint32_t*)&Ch[(size_t)(r + 8) * H_ + cc] = hi;
            *(uint32_t*)&Cl[(size_t)(r + 8) * H_ + cc] = lo;
        }
}

// ===========================================================================
// Causal flash attention, mma.sync + cp.async double-buffered K/V.
// CTA = 128 q rows, 8 warps x 16 rows. Q resident in smem; P in-register.
// smem: Q (Qh 0, Ql 34816) | stage0 @69632 | stage1 @139264 ; stage:
//   Kh 0 | Kl 17408 | Vh 34816 | Vl 52224   (row stride 272)
// ===========================================================================
#define AST     272
#define A_ST0   69632
#define A_STAGE 69632
#define A_SMEM  208896

__global__ __launch_bounds__(256, 1)
void attn_mma(float* __restrict__ out)
{
    extern __shared__ char sm[];
    const uint32_t sb = smem_u32(sm);
    const int tid  = threadIdx.x;
    const int lane = tid & 31;
    const int wid  = tid >> 5;
    const int qb   = (int)(gridDim.x - 1 - blockIdx.x);  // heavy-first
    const int b    = blockIdx.y;

    const int a_r = lane & 15;
    const int a_k = (lane >> 4) * 16;
    const int b_n = (lane & 7) + ((lane >> 4) << 3);
    const int b_k = ((lane >> 3) & 1) * 16;
    const int v_key = lane & 15;
    const int v_h   = (lane >> 4) * 16;

    const size_t qel = ((size_t)b * S_ + (size_t)qb * 128) * H_;

    // Q staging copy (one group)
#pragma unroll
    for (int j = 0; j < 16; j++) {
        int it   = tid + j * 256;
        int tile = it >> 11;              // 0:Qh 1:Ql
        int r    = (it >> 4) & 127;
        int seg  = it & 15;
        const __nv_bfloat16* src =
            (tile ? g_ql : g_qh) + qel + (size_t)r * H_ + seg * 8;
        cpa(sb + tile * 34816 + r * AST + seg * 16, src);
    }
    CP_COMMIT();

    auto issue_kv = [&](int kb, int s) {
        const size_t kel = ((size_t)b * S_ + (size_t)kb * 64) * H_;
        const uint32_t sbase = sb + A_ST0 + s * A_STAGE;
#pragma unroll
        for (int j = 0; j < 16; j++) {
            int it   = tid + j * 256;
            int tile = it >> 10;          // 0:Kh 1:Kl 2:Vh 3:Vl
            int r    = (it >> 4) & 63;
            int seg  = it & 15;
            const __nv_bfloat16* base =
                (tile == 0) ? g_kh : (tile == 1) ? g_kl :
                (tile == 2) ? g_vh : g_vl;
            cpa(sbase + tile * 17408 + r * AST + seg * 16,
                base + kel + (size_t)r * H_ + seg * 8);
        }
    };

    issue_kv(0, 0);
    CP_COMMIT();

    float O[16][4];
#pragma unroll
    for (int nt = 0; nt < 16; nt++)
#pragma unroll
        for (int e = 0; e < 4; e++) O[nt][e] = 0.f;
    float mA = -INFINITY, mB = -INFINITY, lA = 0.f, lB = 0.f;

    const int kb_end = 2 * qb + 1;
    for (int kb = 0; kb <= kb_end; kb++) {
        if (kb + 1 <= kb_end) {
            issue_kv(kb + 1, (kb + 1) & 1);
            CP_COMMIT();
            CP_WAIT(1);
        } else {
            CP_WAIT(0);
        }
        __syncthreads();

        const uint32_t stg = sb + A_ST0 + (kb & 1) * A_STAGE;

        // ---- S = Q K^T ----
        float s[8][4];
#pragma unroll
        for (int nt = 0; nt < 8; nt++)
#pragma unroll
            for (int e = 0; e < 4; e++) s[nt][e] = 0.f;

#pragma unroll
        for (int ks = 0; ks < 8; ks++) {
            const int kbyte = ks * 32;
            uint32_t qh[4], ql[4];
            uint32_t qa = sb + (uint32_t)((wid * 16 + a_r) * AST + kbyte + a_k);
            ldsm4(qh, qa);
            ldsm4(ql, qa + 34816);
            uint32_t kh[8][2], kl[8][2];
#pragma unroll
            for (int ntp = 0; ntp < 4; ntp++) {
                uint32_t ka = stg + (uint32_t)((ntp * 16 + b_n) * AST + kbyte + b_k);
                uint32_t r4[4];
                ldsm4(r4, ka);
                kh[2 * ntp][0] = r4[0]; kh[2 * ntp][1] = r4[1];
                kh[2 * ntp + 1][0] = r4[2]; kh[2 * ntp + 1][1] = r4[3];
                ldsm4(r4, ka + 17408);
                kl[2 * ntp][0] = r4[0]; kl[2 * ntp][1] = r4[1];
                kl[2 * ntp + 1][0] = r4[2]; kl[2 * ntp + 1][1] = r4[3];
            }
#pragma unroll
            for (int nt = 0; nt < 8; nt++) {
                mma16816(s[nt], qh, kh[nt][0], kh[nt][1]);
                mma16816(s[nt], qh, kl[nt][0], kl[nt][1]);
                mma16816(s[nt], ql, kh[nt][0], kh[nt][1]);
            }
        }

        // ---- mask + online softmax ----
        const int grA = qb * 128 + wid * 16 + (lane >> 2);
        if (kb >= 2 * qb) {
#pragma unroll
            for (int nt = 0; nt < 8; nt++) {
                int c0 = kb * 64 + nt * 8 + (lane & 3) * 2;
                if (c0 > grA)         s[nt][0] = -INFINITY;
                if (c0 + 1 > grA)     s[nt][1] = -INFINITY;
                if (c0 > grA + 8)     s[nt][2] = -INFINITY;
                if (c0 + 1 > grA + 8) s[nt][3] = -INFINITY;
            }
        }
        float mxA = -INFINITY, mxB = -INFINITY;
#pragma unroll
        for (int nt = 0; nt < 8; nt++) {
            mxA = fmaxf(mxA, fmaxf(s[nt][0], s[nt][1]));
            mxB = fmaxf(mxB, fmaxf(s[nt][2], s[nt][3]));
        }
        mxA = fmaxf(mxA, __shfl_xor_sync(0xffffffffu, mxA, 1));
        mxA = fmaxf(mxA, __shfl_xor_sync(0xffffffffu, mxA, 2));
        mxB = fmaxf(mxB, __shfl_xor_sync(0xffffffffu, mxB, 1));
        mxB = fmaxf(mxB, __shfl_xor_sync(0xffffffffu, mxB, 2));

        float mnA = fmaxf(mA, mxA), mnB = fmaxf(mB, mxB);
        float alA = __expf(mA - mnA), alB = __expf(mB - mnB);
        float suA = 0.f, suB = 0.f;
#pragma unroll
        for (int nt = 0; nt < 8; nt++) {
            s[nt][0] = __expf(s[nt][0] - mnA);
            s[nt][1] = __expf(s[nt][1] - mnA);
            s[nt][2] = __expf(s[nt][2] - mnB);
            s[nt][3] = __expf(s[nt][3] - mnB);
            suA += s[nt][0] + s[nt][1];
            suB += s[nt][2] + s[nt][3];
        }
        suA += __shfl_xor_sync(0xffffffffu, suA, 1);
        suA += __shfl_xor_sync(0xffffffffu, suA, 2);
        suB += __shfl_xor_sync(0xffffffffu, suB, 1);
        suB += __shfl_xor_sync(0xffffffffu, suB, 2);
        lA = lA * alA + suA;  mA = mnA;
        lB = lB * alB + suB;  mB = mnB;

#pragma unroll
        for (int nt = 0; nt < 16; nt++) {
            O[nt][0] *= alA; O[nt][1] *= alA;
            O[nt][2] *= alB; O[nt][3] *= alB;
        }

        // ---- O += P @ V (P frags built in-register) ----
#pragma unroll
        for (int t = 0; t < 4; t++) {
            uint32_t ph[4], pl[4];
            split2(s[2 * t][0],     s[2 * t][1],     ph[0], pl[0]);
            split2(s[2 * t][2],     s[2 * t][3],     ph[1], pl[1]);
            split2(s[2 * t + 1][0], s[2 * t + 1][1], ph[2], pl[2]);
            split2(s[2 * t + 1][2], s[2 * t + 1][3], ph[3], pl[3]);
#pragma unroll
            for (int ntp = 0; ntp < 8; ntp++) {
                uint32_t va = stg + 34816 +
                    (uint32_t)((t * 16 + v_key) * AST + ntp * 32 + v_h);
                uint32_t vh[4], vl[4];
                ldsm4t(vh, va);
                ldsm4t(vl, va + 17408);
                mma16816(O[2 * ntp],     ph, vh[0], vh[1]);
                mma16816(O[2 * ntp],     ph, vl[0], vl[1]);
                mma16816(O[2 * ntp],     pl, vh[0], vh[1]);
                mma16816(O[2 * ntp + 1], ph, vh[2], vh[3]);
                mma16816(O[2 * ntp + 1], ph, vl[2], vl[3]);
                mma16816(O[2 * ntp + 1], pl, vh[2], vh[3]);
            }
        }
        __syncthreads();   // all warps done with stage (kb&1) before rewrite
    }

    // ---- finalize ----
    const float liA = 1.f / lA, liB = 1.f / lB;
    const int rA = qb * 128 + wid * 16 + (lane >> 2);
#pragma unroll
    for (int nt = 0; nt < 16; nt++) {
        int cc = nt * 8 + (lane & 3) * 2;
        *(float2*)(out + ((size_t)b * S_ + rA) * H_ + cc) =
            make_float2(O[nt][0] * liA, O[nt][1] * liA);
        *(float2*)(out + ((size_t)b * S_ + rA + 8) * H_ + cc) =
            make_float2(O[nt][2] * liB, O[nt][3] * liB);
    }
}

// ===========================================================================
// Launch
// ===========================================================================
extern "C" void kernel_launch(void* const* d_in, const int* in_sizes, int n_in,
                              void* d_out, int out_size)
{
    const float* input = (const float*)d_in[0];
    const float* Wq    = (const float*)d_in[1];
    const float* Wk    = (const float*)d_in[2];
    const float* Wv    = (const float*)d_in[3];
    float* out = (float*)d_out;

    cudaFuncSetAttribute(qkv_mma,
                         cudaFuncAttributeMaxDynamicSharedMemorySize, G_SMEM);
    cudaFuncSetAttribute(attn_mma,
                         cudaFuncAttributeMaxDynamicSharedMemorySize, A_SMEM);

    conv_a<<<(int)((size_t)M_ * D_ / 4 / 256), 256>>>(input);
    conv_w<<<dim3(512, 3), 256>>>(Wq, Wk, Wv);
    qkv_mma<<<dim3(M_ / 128, 3), 256, G_SMEM>>>();
    attn_mma<<<dim3(S_ / 128, B_), 256, A_SMEM>>>(out);
}

// round 14
// speedup vs baseline: 2.7712x; 1.0305x over previous
#include <cuda_runtime.h>
#include <cuda_bf16.h>
#include <math.h>
#include <stdint.h>

#define B_ 16
#define S_ 2048
#define D_ 1024
#define H_ 128
#define M_ (B_ * S_)   // 32768

// Split operands in global (bf16 hi/lo)
__device__ __nv_bfloat16 g_ah[(size_t)M_ * D_];   // input hi
__device__ __nv_bfloat16 g_al[(size_t)M_ * D_];   // input lo
__device__ __nv_bfloat16 g_wth[3 * H_ * D_];      // W transposed [mat][n][k] hi
__device__ __nv_bfloat16 g_wtl[3 * H_ * D_];      // lo
__device__ __nv_bfloat16 g_qh[(size_t)M_ * H_], g_ql[(size_t)M_ * H_];
__device__ __nv_bfloat16 g_kh[(size_t)M_ * H_], g_kl[(size_t)M_ * H_];
__device__ __nv_bfloat16 g_vh[(size_t)M_ * H_], g_vl[(size_t)M_ * H_];

// ===========================================================================
// Helpers
// ===========================================================================
__device__ __forceinline__ uint32_t smem_u32(const void* p) {
    uint32_t a;
    asm("{ .reg .u64 t; cvta.to.shared.u64 t, %1; cvt.u32.u64 %0, t; }"
        : "=r"(a) : "l"(p));
    return a;
}
__device__ __forceinline__ void ldsm4(uint32_t r[4], uint32_t addr) {
    asm volatile("ldmatrix.sync.aligned.m8n8.x4.shared.b16 {%0,%1,%2,%3}, [%4];"
                 : "=r"(r[0]), "=r"(r[1]), "=r"(r[2]), "=r"(r[3]) : "r"(addr));
}
__device__ __forceinline__ void ldsm4t(uint32_t r[4], uint32_t addr) {
    asm volatile("ldmatrix.sync.aligned.m8n8.x4.trans.shared.b16 {%0,%1,%2,%3}, [%4];"
                 : "=r"(r[0]), "=r"(r[1]), "=r"(r[2]), "=r"(r[3]) : "r"(addr));
}
__device__ __forceinline__ void mma16816(float c[4], const uint32_t a[4],
                                         uint32_t b0, uint32_t b1) {
    asm volatile(
        "mma.sync.aligned.m16n8k16.row.col.f32.bf16.bf16.f32 "
        "{%0,%1,%2,%3}, {%4,%5,%6,%7}, {%8,%9}, {%0,%1,%2,%3};"
        : "+f"(c[0]), "+f"(c[1]), "+f"(c[2]), "+f"(c[3])
        : "r"(a[0]), "r"(a[1]), "r"(a[2]), "r"(a[3]), "r"(b0), "r"(b1));
}
__device__ __forceinline__ void split2(float x0, float x1,
                                       uint32_t& hi, uint32_t& lo) {
    __nv_bfloat16 h0 = __float2bfloat16_rn(x0);
    __nv_bfloat16 h1 = __float2bfloat16_rn(x1);
    __nv_bfloat162 hp; hp.x = h0; hp.y = h1;
    hi = *reinterpret_cast<uint32_t*>(&hp);
    __nv_bfloat162 lp = __floats2bfloat162_rn(x0 - __bfloat162float(h0),
                                              x1 - __bfloat162float(h1));
    lo = *reinterpret_cast<uint32_t*>(&lp);
}
__device__ __forceinline__ void cpa(uint32_t dst, const void* src) {
    asm volatile("cp.async.cg.shared.global [%0], [%1], 16;"
                 :: "r"(dst), "l"(src) : "memory");
}
#define CP_COMMIT() asm volatile("cp.async.commit_group;" ::: "memory")
#define CP_WAIT(n)  asm volatile("cp.async.wait_group %0;" :: "n"(n) : "memory")

// ===========================================================================
// Convert kernels: fp32 -> split bf16 (once, outside the hot loops)
// ===========================================================================
__global__ __launch_bounds__(256)
void conv_a(const float* __restrict__ A)
{
    size_t i = ((size_t)blockIdx.x * 256 + threadIdx.x) * 4;
    float4 v = *(const float4*)(A + i);
    uint32_t h0, l0, h1, l1;
    split2(v.x, v.y, h0, l0);
    split2(v.z, v.w, h1, l1);
    *(uint2*)&g_ah[i] = make_uint2(h0, h1);
    *(uint2*)&g_al[i] = make_uint2(l0, l1);
}

__global__ __launch_bounds__(256)
void conv_w(const float* __restrict__ Wq, const float* __restrict__ Wk,
            const float* __restrict__ Wv)
{
    const int mat = blockIdx.y;
    const float* W = (mat == 0) ? Wq : (mat == 1) ? Wk : Wv;
    int idx = blockIdx.x * 256 + threadIdx.x;   // 0..131071
    int k = idx >> 7, n = idx & 127;
    float x = W[(size_t)k * H_ + n];
    __nv_bfloat16 h = __float2bfloat16_rn(x);
    size_t o = (size_t)mat * (H_ * D_) + (size_t)n * D_ + k;
    g_wth[o] = h;
    g_wtl[o] = __float2bfloat16_rn(x - __bfloat162float(h));
}

// ===========================================================================
// QKV GEMM: C[M,H] = A[M,D] @ W[D,H], blockIdx.y selects matrix.
// 256x128 tile, BK=64, 8 warps (4Mx2N, warp tile 64x64), cp.async 2 stages.
// Outputs written as split bf16 (scale folded into Q).
// Stage layout: Ah 0 | Al 36864 | Bh 73728 | Bl 92160 ; stage = 110592
// ===========================================================================
#define GST     144       // smem row stride bytes (64 bf16 + pad)
#define G_STAGE 110592
#define G_SMEM  221184

__global__ __launch_bounds__(256, 1)
void qkv_mma(void)
{
    extern __shared__ char sm[];
    const uint32_t sb = smem_u32(sm);
    const int tid  = threadIdx.x;
    const int lane = tid & 31;
    const int wid  = tid >> 5;
    const int wm   = wid & 3;      // 64-row slice
    const int wn   = wid >> 2;     // 64-col slice
    const int m0   = blockIdx.x * 256;
    const int mat  = blockIdx.y;

    const int a_r = lane & 15;
    const int a_k = (lane >> 4) * 16;
    const int b_n = (lane & 7) + ((lane >> 4) << 3);
    const int b_k = ((lane >> 3) & 1) * 16;

    const __nv_bfloat16* wth = g_wth + (size_t)mat * (H_ * D_);
    const __nv_bfloat16* wtl = g_wtl + (size_t)mat * (H_ * D_);

    auto issue = [&](int c, int s) {
        const int c0 = c * 64;
        const uint32_t sbase = sb + s * G_STAGE;
#pragma unroll
        for (int j = 0; j < 24; j++) {
            int it = tid + j * 256;            // 0..6143
            uint32_t dst;
            const __nv_bfloat16* src;
            if (it < 4096) {                   // A tiles: 2 x 256 rows x 8 segs
                int th  = it >> 11;            // 0:Ah 1:Al
                int r   = (it >> 3) & 255;
                int seg = it & 7;
                src = (th ? g_al : g_ah) + (size_t)(m0 + r) * D_ + c0 + seg * 8;
                dst = sbase + th * 36864 + r * GST + seg * 16;
            } else {                           // B tiles: 2 x 128 rows x 8 segs
                int it2 = it - 4096;
                int th  = it2 >> 10;
                int r   = (it2 >> 3) & 127;
                int seg = it2 & 7;
                src = (th ? wtl : wth) + (size_t)r * D_ + c0 + seg * 8;
                dst = sbase + 73728 + th * 18432 + r * GST + seg * 16;
            }
            cpa(dst, src);
        }
    };

    float acc[4][8][4];
#pragma unroll
    for (int i = 0; i < 4; i++)
#pragma unroll
        for (int j = 0; j < 8; j++)
#pragma unroll
            for (int e = 0; e < 4; e++) acc[i][j][e] = 0.f;

    issue(0, 0);
    CP_COMMIT();

    for (int c = 0; c < 16; c++) {
        if (c + 1 < 16) {
            issue(c + 1, (c + 1) & 1);
            CP_COMMIT();
            CP_WAIT(1);
        } else {
            CP_WAIT(0);
        }
        __syncthreads();

        const uint32_t stg = sb + (c & 1) * G_STAGE;
#pragma unroll
        for (int ks = 0; ks < 4; ks++) {
            const int kb = ks * 32;
            uint32_t ah[4][4], al[4][4];
#pragma unroll
            for (int mt = 0; mt < 4; mt++) {
                uint32_t base = stg + (uint32_t)((wm * 64 + mt * 16 + a_r) * GST + kb + a_k);
                ldsm4(ah[mt], base);
                ldsm4(al[mt], base + 36864);
            }
            uint32_t bh[8][2], bl[8][2];
#pragma unroll
            for (int ntp = 0; ntp < 4; ntp++) {
                uint32_t base = stg + 73728 +
                    (uint32_t)((wn * 64 + ntp * 16 + b_n) * GST + kb + b_k);
                uint32_t r4[4];
                ldsm4(r4, base);
                bh[2 * ntp][0] = r4[0]; bh[2 * ntp][1] = r4[1];
                bh[2 * ntp + 1][0] = r4[2]; bh[2 * ntp + 1][1] = r4[3];
                ldsm4(r4, base + 18432);
                bl[2 * ntp][0] = r4[0]; bl[2 * ntp][1] = r4[1];
                bl[2 * ntp + 1][0] = r4[2]; bl[2 * ntp + 1][1] = r4[3];
            }
#pragma unroll
            for (int mt = 0; mt < 4; mt++)
#pragma unroll
                for (int nt = 0; nt < 8; nt++) {
                    mma16816(acc[mt][nt], ah[mt], bh[nt][0], bh[nt][1]);
                    mma16816(acc[mt][nt], ah[mt], bl[nt][0], bl[nt][1]);
                    mma16816(acc[mt][nt], al[mt], bh[nt][0], bh[nt][1]);
                }
        }
        __syncthreads();
    }

    // Epilogue: write split bf16; fold softmax scale into Q
    const float qs = (mat == 0) ? 0.08838834764831845f : 1.f;
    __nv_bfloat16* Ch = (mat == 0) ? g_qh : (mat == 1) ? g_kh : g_vh;
    __nv_bfloat16* Cl = (mat == 0) ? g_ql : (mat == 1) ? g_kl : g_vl;
#pragma unroll
    for (int mt = 0; mt < 4; mt++)
#pragma unroll
        for (int nt = 0; nt < 8; nt++) {
            int r  = m0 + wm * 64 + mt * 16 + (lane >> 2);
            int cc = wn * 64 + nt * 8 + (lane & 3) * 2;
            uint32_t hi, lo;
            split2(acc[mt][nt][0] * qs, acc[mt][nt][1] * qs, hi, lo);
            *(uint32_t*)&Ch[(size_t)r * H_ + cc] = hi;
            *(uint32_t*)&Cl[(size_t)r * H_ + cc] = lo;
            split2(acc[mt][nt][2] * qs, acc[mt][nt][3] * qs, hi, lo);
            *(uint32_t*)&Ch[(size_t)(r + 8) * H_ + cc] = hi;
            *(uint32_t*)&Cl[(size_t)(r + 8) * H_ + cc] = lo;
        }
}

// ===========================================================================
// Causal flash attention, mma.sync + cp.async double-buffered K/V.
// CTA = 128 q rows, 8 warps x 16 rows. Q resident in smem; P in-register.
// Software-pipelined: K/Q frags double-buffered over ks, V frags over (t,ntp).
// smem: Qh 0 | Ql 34816 | stage0 @69632 | stage1 @139264
// stage: Kh 0 | Kl 17408 | Vh 34816 | Vl 52224   (row stride 272)
// ===========================================================================
#define AST     272
#define A_ST0   69632
#define A_STAGE 69632
#define A_SMEM  208896

__global__ __launch_bounds__(256, 1)
void attn_mma(float* __restrict__ out)
{
    extern __shared__ char sm[];
    const uint32_t sb = smem_u32(sm);
    const int tid  = threadIdx.x;
    const int lane = tid & 31;
    const int wid  = tid >> 5;
    const int qb   = (int)(gridDim.x - 1 - blockIdx.x);  // heavy-first
    const int b    = blockIdx.y;

    const int a_r = lane & 15;
    const int a_k = (lane >> 4) * 16;
    const int b_n = (lane & 7) + ((lane >> 4) << 3);
    const int b_k = ((lane >> 3) & 1) * 16;
    const int v_key = lane & 15;
    const int v_h   = (lane >> 4) * 16;

    const size_t qel = ((size_t)b * S_ + (size_t)qb * 128) * H_;

    // Q staging copy (one group)
#pragma unroll
    for (int j = 0; j < 16; j++) {
        int it   = tid + j * 256;
        int tile = it >> 11;              // 0:Qh 1:Ql
        int r    = (it >> 4) & 127;
        int seg  = it & 15;
        const __nv_bfloat16* src =
            (tile ? g_ql : g_qh) + qel + (size_t)r * H_ + seg * 8;
        cpa(sb + tile * 34816 + r * AST + seg * 16, src);
    }
    CP_COMMIT();

    auto issue_kv = [&](int kb, int s) {
        const size_t kel = ((size_t)b * S_ + (size_t)kb * 64) * H_;
        const uint32_t sbase = sb + A_ST0 + s * A_STAGE;
#pragma unroll
        for (int j = 0; j < 16; j++) {
            int it   = tid + j * 256;
            int tile = it >> 10;          // 0:Kh 1:Kl 2:Vh 3:Vl
            int r    = (it >> 4) & 63;
            int seg  = it & 15;
            const __nv_bfloat16* base =
                (tile == 0) ? g_kh : (tile == 1) ? g_kl :
                (tile == 2) ? g_vh : g_vl;
            cpa(sbase + tile * 17408 + r * AST + seg * 16,
                base + kel + (size_t)r * H_ + seg * 8);
        }
    };

    issue_kv(0, 0);
    CP_COMMIT();

    float O[16][4];
#pragma unroll
    for (int nt = 0; nt < 16; nt++)
#pragma unroll
        for (int e = 0; e < 4; e++) O[nt][e] = 0.f;
    float mA = -INFINITY, mB = -INFINITY, lA = 0.f, lB = 0.f;

    const int kb_end = 2 * qb + 1;
    for (int kb = 0; kb <= kb_end; kb++) {
        if (kb + 1 <= kb_end) {
            issue_kv(kb + 1, (kb + 1) & 1);
            CP_COMMIT();
            CP_WAIT(1);
        } else {
            CP_WAIT(0);
        }
        __syncthreads();

        const uint32_t stg = sb + A_ST0 + (kb & 1) * A_STAGE;

        // ---- S = Q K^T (software-pipelined over ks) ----
        float s[8][4];
#pragma unroll
        for (int nt = 0; nt < 8; nt++)
#pragma unroll
            for (int e = 0; e < 4; e++) s[nt][e] = 0.f;

        uint32_t qhB[2][4], qlB[2][4], khB[2][8][2], klB[2][8][2];
        auto ldk = [&](int ks, int bu) {
            const int kbyte = ks * 32;
            uint32_t qa = sb + (uint32_t)((wid * 16 + a_r) * AST + kbyte + a_k);
            ldsm4(qhB[bu], qa);
            ldsm4(qlB[bu], qa + 34816);
#pragma unroll
            for (int ntp = 0; ntp < 4; ntp++) {
                uint32_t ka = stg + (uint32_t)((ntp * 16 + b_n) * AST + kbyte + b_k);
                uint32_t r4[4];
                ldsm4(r4, ka);
                khB[bu][2 * ntp][0] = r4[0]; khB[bu][2 * ntp][1] = r4[1];
                khB[bu][2 * ntp + 1][0] = r4[2]; khB[bu][2 * ntp + 1][1] = r4[3];
                ldsm4(r4, ka + 17408);
                klB[bu][2 * ntp][0] = r4[0]; klB[bu][2 * ntp][1] = r4[1];
                klB[bu][2 * ntp + 1][0] = r4[2]; klB[bu][2 * ntp + 1][1] = r4[3];
            }
        };
        ldk(0, 0);
#pragma unroll
        for (int ks = 0; ks < 8; ks++) {
            const int cur = ks & 1;
            if (ks < 7) ldk(ks + 1, cur ^ 1);
#pragma unroll
            for (int nt = 0; nt < 8; nt++) {
                mma16816(s[nt], qhB[cur], khB[cur][nt][0], khB[cur][nt][1]);
                mma16816(s[nt], qhB[cur], klB[cur][nt][0], klB[cur][nt][1]);
                mma16816(s[nt], qlB[cur], khB[cur][nt][0], khB[cur][nt][1]);
            }
        }

        // ---- mask + online softmax ----
        const int grA = qb * 128 + wid * 16 + (lane >> 2);
        if (kb >= 2 * qb) {
#pragma unroll
            for (int nt = 0; nt < 8; nt++) {
                int c0 = kb * 64 + nt * 8 + (lane & 3) * 2;
                if (c0 > grA)         s[nt][0] = -INFINITY;
                if (c0 + 1 > grA)     s[nt][1] = -INFINITY;
                if (c0 > grA + 8)     s[nt][2] = -INFINITY;
                if (c0 + 1 > grA + 8) s[nt][3] = -INFINITY;
            }
        }
        float mxA = -INFINITY, mxB = -INFINITY;
#pragma unroll
        for (int nt = 0; nt < 8; nt++) {
            mxA = fmaxf(mxA, fmaxf(s[nt][0], s[nt][1]));
            mxB = fmaxf(mxB, fmaxf(s[nt][2], s[nt][3]));
        }
        mxA = fmaxf(mxA, __shfl_xor_sync(0xffffffffu, mxA, 1));
        mxA = fmaxf(mxA, __shfl_xor_sync(0xffffffffu, mxA, 2));
        mxB = fmaxf(mxB, __shfl_xor_sync(0xffffffffu, mxB, 1));
        mxB = fmaxf(mxB, __shfl_xor_sync(0xffffffffu, mxB, 2));

        float mnA = fmaxf(mA, mxA), mnB = fmaxf(mB, mxB);
        float alA = __expf(mA - mnA), alB = __expf(mB - mnB);
        float suA = 0.f, suB = 0.f;
#pragma unroll
        for (int nt = 0; nt < 8; nt++) {
            s[nt][0] = __expf(s[nt][0] - mnA);
            s[nt][1] = __expf(s[nt][1] - mnA);
            s[nt][2] = __expf(s[nt][2] - mnB);
            s[nt][3] = __expf(s[nt][3] - mnB);
            suA += s[nt][0] + s[nt][1];
            suB += s[nt][2] + s[nt][3];
        }
        suA += __shfl_xor_sync(0xffffffffu, suA, 1);
        suA += __shfl_xor_sync(0xffffffffu, suA, 2);
        suB += __shfl_xor_sync(0xffffffffu, suB, 1);
        suB += __shfl_xor_sync(0xffffffffu, suB, 2);
        lA = lA * alA + suA;  mA = mnA;
        lB = lB * alB + suB;  mB = mnB;

#pragma unroll
        for (int nt = 0; nt < 16; nt++) {
            O[nt][0] *= alA; O[nt][1] *= alA;
            O[nt][2] *= alB; O[nt][3] *= alB;
        }

        // ---- O += P @ V (P in-register; V frags pipelined over (t,ntp)) ----
        uint32_t vhB[2][4], vlB[2][4];
        auto ldv = [&](int t, int ntp, int bu) {
            uint32_t va = stg + 34816 +
                (uint32_t)((t * 16 + v_key) * AST + ntp * 32 + v_h);
            ldsm4t(vhB[bu], va);
            ldsm4t(vlB[bu], va + 17408);
        };
        ldv(0, 0, 0);
#pragma unroll
        for (int t = 0; t < 4; t++) {
            uint32_t ph[4], pl[4];
            split2(s[2 * t][0],     s[2 * t][1],     ph[0], pl[0]);
            split2(s[2 * t][2],     s[2 * t][3],     ph[1], pl[1]);
            split2(s[2 * t + 1][0], s[2 * t + 1][1], ph[2], pl[2]);
            split2(s[2 * t + 1][2], s[2 * t + 1][3], ph[3], pl[3]);
#pragma unroll
            for (int ntp = 0; ntp < 8; ntp++) {
                const int f = t * 8 + ntp;
                const int cur = f & 1;
                if (f < 31) ldv((f + 1) >> 3, (f + 1) & 7, cur ^ 1);
                mma16816(O[2 * ntp],     ph, vhB[cur][0], vhB[cur][1]);
                mma16816(O[2 * ntp],     ph, vlB[cur][0], vlB[cur][1]);
                mma16816(O[2 * ntp],     pl, vhB[cur][0], vhB[cur][1]);
                mma16816(O[2 * ntp + 1], ph, vhB[cur][2], vhB[cur][3]);
                mma16816(O[2 * ntp + 1], ph, vlB[cur][2], vlB[cur][3]);
                mma16816(O[2 * ntp + 1], pl, vhB[cur][2], vhB[cur][3]);
            }
        }
        __syncthreads();   // all warps done with stage (kb&1) before rewrite
    }

    // ---- finalize ----
    const float liA = 1.f / lA, liB = 1.f / lB;
    const int rA = qb * 128 + wid * 16 + (lane >> 2);
#pragma unroll
    for (int nt = 0; nt < 16; nt++) {
        int cc = nt * 8 + (lane & 3) * 2;
        *(float2*)(out + ((size_t)b * S_ + rA) * H_ + cc) =
            make_float2(O[nt][0] * liA, O[nt][1] * liA);
        *(float2*)(out + ((size_t)b * S_ + rA + 8) * H_ + cc) =
            make_float2(O[nt][2] * liB, O[nt][3] * liB);
    }
}

// ===========================================================================
// Launch
// ===========================================================================
extern "C" void kernel_launch(void* const* d_in, const int* in_sizes, int n_in,
                              void* d_out, int out_size)
{
    const float* input = (const float*)d_in[0];
    const float* Wq    = (const float*)d_in[1];
    const float* Wk    = (const float*)d_in[2];
    const float* Wv    = (const float*)d_in[3];
    float* out = (float*)d_out;

    cudaFuncSetAttribute(qkv_mma,
                         cudaFuncAttributeMaxDynamicSharedMemorySize, G_SMEM);
    cudaFuncSetAttribute(attn_mma,
                         cudaFuncAttributeMaxDynamicSharedMemorySize, A_SMEM);

    conv_a<<<(int)((size_t)M_ * D_ / 4 / 256), 256>>>(input);
    conv_w<<<dim3(512, 3), 256>>>(Wq, Wk, Wv);
    qkv_mma<<<dim3(M_ / 256, 3), 256, G_SMEM>>>();
    attn_mma<<<dim3(S_ / 128, B_), 256, A_SMEM>>>(out);
}